// round 1
// baseline (speedup 1.0000x reference)
#include <cuda_runtime.h>

#define Bn 8
#define Sn 2048
#define Dn 256
#define Hn 4
#define DHn 64

// ---------------- scratch (static device arrays; no allocation) ----------------
__device__ float g_qs[Bn*Hn*Sn*DHn];     // 16 MB  [B,H,S,DH]
__device__ float g_ks[Bn*Hn*Sn*DHn];     // 16 MB  [B,H,S,DH]
__device__ float g_vs[Bn*Sn*DHn];        //  4 MB  [B,S,DH]
__device__ float g_heads[Bn*Hn*Sn*DHn];  // 16 MB  [B,H,S,DH]  (already scaled by 1/(4*rowsum))
__device__ float g_rowsum[Bn*Hn*Sn];     // 256 KB

// ---------------- tf32 helpers ----------------
__device__ __forceinline__ unsigned f2tf(float x) {
    unsigned u;
    asm("cvt.rna.tf32.f32 %0, %1;" : "=r"(u) : "f"(x));
    return u;
}
__device__ __forceinline__ void split2(float x, unsigned &hi, unsigned &lo) {
    hi = f2tf(x);
    lo = f2tf(x - __uint_as_float(hi));
}
__device__ __forceinline__ void mma8(float* c, const unsigned* a, const unsigned* b) {
    asm volatile("mma.sync.aligned.m16n8k8.row.col.f32.tf32.tf32.f32 "
        "{%0,%1,%2,%3}, {%4,%5,%6,%7}, {%8,%9}, {%0,%1,%2,%3};\n"
        : "+f"(c[0]), "+f"(c[1]), "+f"(c[2]), "+f"(c[3])
        : "r"(a[0]), "r"(a[1]), "r"(a[2]), "r"(a[3]), "r"(b[0]), "r"(b[1]));
}

// ================= Kernel 1: projections (qs, ks, vs) via tf32x3 GEMM =================
// z=0: qs = q @ Wq[h]   z=1: ks = k @ Wk[h]   z=2: vs = v @ Wv
// Tile: 128 (M) x 64 (N) x 32 (Kchunk). 8 warps as 4x2, warp tile 32x32.
__global__ __launch_bounds__(256) void proj_kernel(
    const float* __restrict__ q, const float* __restrict__ k, const float* __restrict__ v,
    const float* __restrict__ Wq, const float* __restrict__ Wk, const float* __restrict__ Wv)
{
    int z = blockIdx.z;
    if (z == 2 && blockIdx.x > 0) return;
    __shared__ float As[128][36];
    __shared__ float Bs[32][72];

    const float* X = (z == 0) ? q : (z == 1) ? k : v;
    const float* W = (z == 0) ? (Wq + (size_t)blockIdx.x * Dn * DHn)
                   : (z == 1) ? (Wk + (size_t)blockIdx.x * Dn * DHn) : Wv;
    int M0 = blockIdx.y * 128;
    int tid = threadIdx.x;
    int warp = tid >> 5, lane = tid & 31;
    int g = lane >> 2, t = lane & 3;
    int wm0 = (warp >> 1) * 32, wn0 = (warp & 1) * 32;

    float c[2][4][4];
    #pragma unroll
    for (int mt = 0; mt < 2; mt++)
        #pragma unroll
        for (int nt = 0; nt < 4; nt++)
            #pragma unroll
            for (int i = 0; i < 4; i++) c[mt][nt][i] = 0.f;

    for (int kc = 0; kc < 8; kc++) {
        int K0 = kc * 32;
        #pragma unroll
        for (int it = 0; it < 4; it++) {
            int i = tid + it * 256;
            int r = i >> 3, c4 = (i & 7) << 2;
            float4 val = *reinterpret_cast<const float4*>(&X[(size_t)(M0 + r) * Dn + K0 + c4]);
            As[r][c4] = val.x; As[r][c4+1] = val.y; As[r][c4+2] = val.z; As[r][c4+3] = val.w;
        }
        #pragma unroll
        for (int it = 0; it < 2; it++) {
            int i = tid + it * 256;
            int r = i >> 4, c4 = (i & 15) << 2;
            float4 val = *reinterpret_cast<const float4*>(&W[(size_t)(K0 + r) * DHn + c4]);
            Bs[r][c4] = val.x; Bs[r][c4+1] = val.y; Bs[r][c4+2] = val.z; Bs[r][c4+3] = val.w;
        }
        __syncthreads();
        #pragma unroll
        for (int kk = 0; kk < 4; kk++) {
            int k0 = kk * 8;
            unsigned ah[2][4], al[2][4], bh[4][2], bl[4][2];
            #pragma unroll
            for (int mt = 0; mt < 2; mt++) {
                int rb = wm0 + mt * 16;
                split2(As[rb + g][k0 + t],         ah[mt][0], al[mt][0]);
                split2(As[rb + 8 + g][k0 + t],     ah[mt][1], al[mt][1]);
                split2(As[rb + g][k0 + t + 4],     ah[mt][2], al[mt][2]);
                split2(As[rb + 8 + g][k0 + t + 4], ah[mt][3], al[mt][3]);
            }
            #pragma unroll
            for (int nt = 0; nt < 4; nt++) {
                int cb = wn0 + nt * 8;
                split2(Bs[k0 + t][cb + g],     bh[nt][0], bl[nt][0]);
                split2(Bs[k0 + t + 4][cb + g], bh[nt][1], bl[nt][1]);
            }
            #pragma unroll
            for (int mt = 0; mt < 2; mt++)
                #pragma unroll
                for (int nt = 0; nt < 4; nt++) {
                    mma8(c[mt][nt], ah[mt], bh[nt]);
                    mma8(c[mt][nt], ah[mt], bl[nt]);
                    mma8(c[mt][nt], al[mt], bh[nt]);
                }
        }
        __syncthreads();
    }
    // store, converting [row, col] -> [B,H,S,DH] (or [B,S,DH] for vs)
    #pragma unroll
    for (int mt = 0; mt < 2; mt++)
        #pragma unroll
        for (int nt = 0; nt < 4; nt++) {
            int e = wn0 + nt * 8 + 2 * t;
            #pragma unroll
            for (int half = 0; half < 2; half++) {
                int r = M0 + wm0 + mt * 16 + half * 8 + g;
                int bb = r >> 11, s = r & 2047;
                float2 val = make_float2(c[mt][nt][half * 2], c[mt][nt][half * 2 + 1]);
                if (z == 2) {
                    *reinterpret_cast<float2*>(&g_vs[((size_t)bb * Sn + s) * DHn + e]) = val;
                } else {
                    float* dst = (z == 0) ? g_qs : g_ks;
                    int h = blockIdx.x;
                    *reinterpret_cast<float2*>(&dst[(((size_t)(bb * Hn + h)) * Sn + s) * DHn + e]) = val;
                }
            }
        }
}

// ================= Kernel 2: fused attention =================
// CTA: (b,h, 128 S-rows). Loops 32 chunks of 64 T-cols.
//   S = Q@K^T (tf32x3), p = mask ? exp(S/8) : 0, write p to attn (unnormalized),
//   accumulate rowsum, heads += P@V (tf32). At end: heads scaled by 0.25/rowsum.
__global__ __launch_bounds__(256) void attn_kernel(
    const int* __restrict__ mask, float* __restrict__ attn_out)
{
    extern __shared__ float sm[];
    float (*Qs)[68] = reinterpret_cast<float(*)[68]>(sm);                 // 128x68
    float (*Ks)[68] = reinterpret_cast<float(*)[68]>(sm + 8704);          // 64x68
    float (*Vs)[72] = reinterpret_cast<float(*)[72]>(sm + 8704 + 4352);   // 64x72
    float (*Ps)[68] = reinterpret_cast<float(*)[68]>(sm + 8704 + 4352 + 4608); // 128x68
    float* rowsum = sm + 8704 + 4352 + 4608 + 8704;                       // 128

    int st = blockIdx.x, h = blockIdx.y, b = blockIdx.z;
    int bh = b * Hn + h;
    int S0 = st * 128;
    int tid = threadIdx.x, warp = tid >> 5, lane = tid & 31;
    int g = lane >> 2, t = lane & 3;
    int wm0 = (warp >> 1) * 32, wn0 = (warp & 1) * 32;

    const float* qsrc = g_qs + ((size_t)bh * Sn + S0) * DHn;
    const float* ksrc = g_ks + (size_t)bh * Sn * DHn;
    const float* vsrc = g_vs + (size_t)b * Sn * DHn;
    const int*   msrc = mask + (size_t)b * Sn * Sn;
    float*       aout = attn_out + (size_t)bh * Sn * Sn;

    #pragma unroll
    for (int it = 0; it < 8; it++) {
        int i = tid + it * 256;
        int r = i >> 4, c4 = (i & 15) << 2;
        float4 val = *reinterpret_cast<const float4*>(&qsrc[(size_t)r * DHn + c4]);
        Qs[r][c4] = val.x; Qs[r][c4+1] = val.y; Qs[r][c4+2] = val.z; Qs[r][c4+3] = val.w;
    }
    if (tid < 128) rowsum[tid] = 0.f;

    float cO[2][4][4];
    #pragma unroll
    for (int mt = 0; mt < 2; mt++)
        #pragma unroll
        for (int nt = 0; nt < 4; nt++)
            #pragma unroll
            for (int i = 0; i < 4; i++) cO[mt][nt][i] = 0.f;
    float rpart[2][2] = {{0.f, 0.f}, {0.f, 0.f}};

    for (int tc = 0; tc < 32; tc++) {
        int T0 = tc * 64;
        #pragma unroll
        for (int it = 0; it < 4; it++) {
            int i = tid + it * 256;
            int r = i >> 4, c4 = (i & 15) << 2;
            float4 kv = *reinterpret_cast<const float4*>(&ksrc[(size_t)(T0 + r) * DHn + c4]);
            Ks[r][c4] = kv.x; Ks[r][c4+1] = kv.y; Ks[r][c4+2] = kv.z; Ks[r][c4+3] = kv.w;
            float4 vv = *reinterpret_cast<const float4*>(&vsrc[(size_t)(T0 + r) * DHn + c4]);
            Vs[r][c4] = vv.x; Vs[r][c4+1] = vv.y; Vs[r][c4+2] = vv.z; Vs[r][c4+3] = vv.w;
        }
        __syncthreads();

        // ---- QK^T (tf32x3) ----
        float cS[2][4][4];
        #pragma unroll
        for (int mt = 0; mt < 2; mt++)
            #pragma unroll
            for (int nt = 0; nt < 4; nt++)
                #pragma unroll
                for (int i = 0; i < 4; i++) cS[mt][nt][i] = 0.f;
        #pragma unroll
        for (int kk = 0; kk < 8; kk++) {
            int k0 = kk * 8;
            unsigned ah[2][4], al[2][4], bhf[4][2], blf[4][2];
            #pragma unroll
            for (int mt = 0; mt < 2; mt++) {
                int rb = wm0 + mt * 16;
                split2(Qs[rb + g][k0 + t],         ah[mt][0], al[mt][0]);
                split2(Qs[rb + 8 + g][k0 + t],     ah[mt][1], al[mt][1]);
                split2(Qs[rb + g][k0 + t + 4],     ah[mt][2], al[mt][2]);
                split2(Qs[rb + 8 + g][k0 + t + 4], ah[mt][3], al[mt][3]);
            }
            #pragma unroll
            for (int nt = 0; nt < 4; nt++) {
                int rb = wn0 + nt * 8 + g;
                split2(Ks[rb][k0 + t],     bhf[nt][0], blf[nt][0]);
                split2(Ks[rb][k0 + t + 4], bhf[nt][1], blf[nt][1]);
            }
            #pragma unroll
            for (int mt = 0; mt < 2; mt++)
                #pragma unroll
                for (int nt = 0; nt < 4; nt++) {
                    mma8(cS[mt][nt], ah[mt], bhf[nt]);
                    mma8(cS[mt][nt], ah[mt], blf[nt]);
                    mma8(cS[mt][nt], al[mt], bhf[nt]);
                }
        }

        // ---- mask + exp + write attn (unnormalized) + stage P ----
        #pragma unroll
        for (int mt = 0; mt < 2; mt++)
            #pragma unroll
            for (int nt = 0; nt < 4; nt++) {
                int tloc = wn0 + nt * 8 + 2 * t;
                int tg = T0 + tloc;
                #pragma unroll
                for (int half = 0; half < 2; half++) {
                    int rloc = wm0 + mt * 16 + half * 8 + g;
                    int sg = S0 + rloc;
                    int2 mv = *reinterpret_cast<const int2*>(&msrc[(size_t)sg * Sn + tg]);
                    float p0 = mv.x ? __expf(cS[mt][nt][half * 2]     * 0.125f) : 0.f;
                    float p1 = mv.y ? __expf(cS[mt][nt][half * 2 + 1] * 0.125f) : 0.f;
                    *reinterpret_cast<float2*>(&aout[(size_t)sg * Sn + tg]) = make_float2(p0, p1);
                    *reinterpret_cast<float2*>(&Ps[rloc][tloc]) = make_float2(p0, p1);
                    rpart[mt][half] += p0 + p1;
                }
            }
        __syncthreads();

        // ---- heads += P @ V (tf32) ----
        #pragma unroll
        for (int kk = 0; kk < 8; kk++) {
            int k0 = kk * 8;
            unsigned a[2][4], bf[4][2];
            #pragma unroll
            for (int mt = 0; mt < 2; mt++) {
                int rb = wm0 + mt * 16;
                a[mt][0] = f2tf(Ps[rb + g][k0 + t]);
                a[mt][1] = f2tf(Ps[rb + 8 + g][k0 + t]);
                a[mt][2] = f2tf(Ps[rb + g][k0 + t + 4]);
                a[mt][3] = f2tf(Ps[rb + 8 + g][k0 + t + 4]);
            }
            #pragma unroll
            for (int nt = 0; nt < 4; nt++) {
                int cb = wn0 + nt * 8 + g;
                bf[nt][0] = f2tf(Vs[k0 + t][cb]);
                bf[nt][1] = f2tf(Vs[k0 + t + 4][cb]);
            }
            #pragma unroll
            for (int mt = 0; mt < 2; mt++)
                #pragma unroll
                for (int nt = 0; nt < 4; nt++)
                    mma8(cO[mt][nt], a[mt], bf[nt]);
        }
        __syncthreads();
    }

    // ---- rowsum reduce ----
    #pragma unroll
    for (int mt = 0; mt < 2; mt++)
        #pragma unroll
        for (int half = 0; half < 2; half++) {
            float v = rpart[mt][half];
            v += __shfl_xor_sync(0xffffffffu, v, 1);
            v += __shfl_xor_sync(0xffffffffu, v, 2);
            if (t == 0) atomicAdd(&rowsum[wm0 + mt * 16 + half * 8 + g], v);
        }
    __syncthreads();

    // ---- write heads (scaled by 0.25/rowsum) + rowsum ----
    float* hdst = g_heads + (size_t)bh * Sn * DHn;
    #pragma unroll
    for (int mt = 0; mt < 2; mt++)
        #pragma unroll
        for (int nt = 0; nt < 4; nt++) {
            int e = wn0 + nt * 8 + 2 * t;
            #pragma unroll
            for (int half = 0; half < 2; half++) {
                int rloc = wm0 + mt * 16 + half * 8 + g;
                float inv = 0.25f / rowsum[rloc];
                float2 val = make_float2(cO[mt][nt][half * 2] * inv, cO[mt][nt][half * 2 + 1] * inv);
                *reinterpret_cast<float2*>(&hdst[(size_t)(S0 + rloc) * DHn + e]) = val;
            }
        }
    if (tid < 128) g_rowsum[(size_t)bh * Sn + S0 + tid] = rowsum[tid];
}

// ================= Kernel 3: normalize attn rows =================
__global__ void rescale_kernel(float* __restrict__ attn) {
    int row = blockIdx.x;
    float inv = 1.f / g_rowsum[row];
    float4* p = reinterpret_cast<float4*>(attn + (size_t)row * Sn);
    int tid = threadIdx.x;
    #pragma unroll
    for (int i = 0; i < 2; i++) {
        float4 v = p[tid + i * 256];
        v.x *= inv; v.y *= inv; v.z *= inv; v.w *= inv;
        p[tid + i * 256] = v;
    }
}

// ================= Kernel 4: out = mean_h(heads) @ Wo =================
__global__ __launch_bounds__(256) void final_kernel(
    const float* __restrict__ Wo, float* __restrict__ out)
{
    __shared__ float avg[16][64];
    int r0 = blockIdx.x * 16;
    int tid = threadIdx.x;
    #pragma unroll
    for (int it = 0; it < 4; it++) {
        int i = tid + it * 256;
        int rr = i >> 6, e = i & 63;
        int R = r0 + rr;
        int bb = R >> 11, s = R & 2047;
        size_t base = ((size_t)(bb * Hn) * Sn + s) * DHn + e;
        // heads already carry the 1/(4*rowsum) factor
        avg[rr][e] = g_heads[base] + g_heads[base + (size_t)Sn * DHn]
                   + g_heads[base + 2 * (size_t)Sn * DHn] + g_heads[base + 3 * (size_t)Sn * DHn];
    }
    __syncthreads();
    float acc[16];
    #pragma unroll
    for (int i = 0; i < 16; i++) acc[i] = 0.f;
    int d = tid;
    #pragma unroll 16
    for (int e = 0; e < 64; e++) {
        float w = Wo[e * Dn + d];
        #pragma unroll
        for (int i = 0; i < 16; i++) acc[i] += avg[i][e] * w;
    }
    #pragma unroll
    for (int i = 0; i < 16; i++) out[(size_t)(r0 + i) * Dn + d] = acc[i];
}

// ================= launch =================
extern "C" void kernel_launch(void* const* d_in, const int* in_sizes, int n_in,
                              void* d_out, int out_size) {
    const float* q    = (const float*)d_in[0];
    const float* k    = (const float*)d_in[1];
    const float* v    = (const float*)d_in[2];
    const int*   mask = (const int*)  d_in[3];
    const float* Wq   = (const float*)d_in[4];
    const float* Wk   = (const float*)d_in[5];
    const float* Wv   = (const float*)d_in[6];
    const float* Wo   = (const float*)d_in[7];
    float* outp  = (float*)d_out;
    float* attnp = outp + (size_t)Bn * Sn * Dn;   // outputs first, attn second

    (void)in_sizes; (void)n_in; (void)out_size;

    cudaFuncSetAttribute(attn_kernel, cudaFuncAttributeMaxDynamicSharedMemorySize, 105984);

    proj_kernel<<<dim3(4, 128, 3), 256>>>(q, k, v, Wq, Wk, Wv);
    attn_kernel<<<dim3(16, 4, 8), 256, 105984>>>(mask, attnp);
    rescale_kernel<<<Bn * Hn * Sn, 256>>>(attnp);
    final_kernel<<<(Bn * Sn) / 16, 256>>>(Wo, outp);
}

// round 3
// speedup vs baseline: 1.2039x; 1.2039x over previous
#include <cuda_runtime.h>
#include <cuda_bf16.h>

#define Bn 8
#define Sn 2048
#define Dn 256
#define Hn 4
#define DHn 64

// ---------------- scratch (static device arrays; no allocation) ----------------
__device__ float g_qs[Bn*Hn*Sn*DHn];     // 16 MB  [B,H,S,DH]
__device__ float g_ks[Bn*Hn*Sn*DHn];     // 16 MB  [B,H,S,DH]
__device__ float g_vs[Bn*Sn*DHn];        //  4 MB  [B,S,DH]
__device__ float g_heads[Bn*Hn*Sn*DHn];  // 16 MB  [B,H,S,DH]  (already scaled by 1/(4*rowsum))
__device__ float g_rowsum[Bn*Hn*Sn];     // 256 KB
__device__ unsigned g_mbits[Bn*Sn*(Sn/32)]; // 16.8 MB bit-packed mask

// ---------------- tf32 helpers ----------------
__device__ __forceinline__ unsigned f2tf(float x) {
    unsigned u;
    asm("cvt.rna.tf32.f32 %0, %1;" : "=r"(u) : "f"(x));
    return u;
}
__device__ __forceinline__ void split2(float x, unsigned &hi, unsigned &lo) {
    hi = f2tf(x);
    lo = f2tf(x - __uint_as_float(hi));
}
__device__ __forceinline__ void mma8(float* c, const unsigned* a, const unsigned* b) {
    asm volatile("mma.sync.aligned.m16n8k8.row.col.f32.tf32.tf32.f32 "
        "{%0,%1,%2,%3}, {%4,%5,%6,%7}, {%8,%9}, {%0,%1,%2,%3};\n"
        : "+f"(c[0]), "+f"(c[1]), "+f"(c[2]), "+f"(c[3])
        : "r"(a[0]), "r"(a[1]), "r"(a[2]), "r"(a[3]), "r"(b[0]), "r"(b[1]));
}
__device__ __forceinline__ void mma16(float* c, const unsigned* a, const unsigned* b) {
    asm volatile("mma.sync.aligned.m16n8k16.row.col.f32.bf16.bf16.f32 "
        "{%0,%1,%2,%3}, {%4,%5,%6,%7}, {%8,%9}, {%0,%1,%2,%3};\n"
        : "+f"(c[0]), "+f"(c[1]), "+f"(c[2]), "+f"(c[3])
        : "r"(a[0]), "r"(a[1]), "r"(a[2]), "r"(a[3]), "r"(b[0]), "r"(b[1]));
}
__device__ __forceinline__ void bsplit(float x, __nv_bfloat16 &hi, __nv_bfloat16 &lo) {
    hi = __float2bfloat16_rn(x);
    lo = __float2bfloat16_rn(x - __bfloat162float(hi));
}

// ================= Kernel 0: bit-pack the mask =================
__global__ void pack_mask_kernel(const int* __restrict__ mask) {
    size_t i = (size_t)blockIdx.x * 256 + threadIdx.x;
    int m = mask[i] != 0;
    unsigned bal = __ballot_sync(0xffffffffu, m);
    if ((threadIdx.x & 31) == 0) g_mbits[i >> 5] = bal;
}

// ================= Kernel 1: projections (qs, ks, vs) via tf32x3 GEMM =================
__global__ __launch_bounds__(256) void proj_kernel(
    const float* __restrict__ q, const float* __restrict__ k, const float* __restrict__ v,
    const float* __restrict__ Wq, const float* __restrict__ Wk, const float* __restrict__ Wv)
{
    int z = blockIdx.z;
    if (z == 2 && blockIdx.x > 0) return;
    __shared__ float As[128][36];
    __shared__ float Bs[32][72];

    const float* X = (z == 0) ? q : (z == 1) ? k : v;
    const float* W = (z == 0) ? (Wq + (size_t)blockIdx.x * Dn * DHn)
                   : (z == 1) ? (Wk + (size_t)blockIdx.x * Dn * DHn) : Wv;
    int M0 = blockIdx.y * 128;
    int tid = threadIdx.x;
    int warp = tid >> 5, lane = tid & 31;
    int g = lane >> 2, t = lane & 3;
    int wm0 = (warp >> 1) * 32, wn0 = (warp & 1) * 32;

    float c[2][4][4];
    #pragma unroll
    for (int mt = 0; mt < 2; mt++)
        #pragma unroll
        for (int nt = 0; nt < 4; nt++)
            #pragma unroll
            for (int i = 0; i < 4; i++) c[mt][nt][i] = 0.f;

    for (int kc = 0; kc < 8; kc++) {
        int K0 = kc * 32;
        #pragma unroll
        for (int it = 0; it < 4; it++) {
            int i = tid + it * 256;
            int r = i >> 3, c4 = (i & 7) << 2;
            float4 val = *reinterpret_cast<const float4*>(&X[(size_t)(M0 + r) * Dn + K0 + c4]);
            As[r][c4] = val.x; As[r][c4+1] = val.y; As[r][c4+2] = val.z; As[r][c4+3] = val.w;
        }
        #pragma unroll
        for (int it = 0; it < 2; it++) {
            int i = tid + it * 256;
            int r = i >> 4, c4 = (i & 15) << 2;
            float4 val = *reinterpret_cast<const float4*>(&W[(size_t)(K0 + r) * DHn + c4]);
            Bs[r][c4] = val.x; Bs[r][c4+1] = val.y; Bs[r][c4+2] = val.z; Bs[r][c4+3] = val.w;
        }
        __syncthreads();
        #pragma unroll
        for (int kk = 0; kk < 4; kk++) {
            int k0 = kk * 8;
            unsigned ah[2][4], al[2][4], bh[4][2], bl[4][2];
            #pragma unroll
            for (int mt = 0; mt < 2; mt++) {
                int rb = wm0 + mt * 16;
                split2(As[rb + g][k0 + t],         ah[mt][0], al[mt][0]);
                split2(As[rb + 8 + g][k0 + t],     ah[mt][1], al[mt][1]);
                split2(As[rb + g][k0 + t + 4],     ah[mt][2], al[mt][2]);
                split2(As[rb + 8 + g][k0 + t + 4], ah[mt][3], al[mt][3]);
            }
            #pragma unroll
            for (int nt = 0; nt < 4; nt++) {
                int cb = wn0 + nt * 8;
                split2(Bs[k0 + t][cb + g],     bh[nt][0], bl[nt][0]);
                split2(Bs[k0 + t + 4][cb + g], bh[nt][1], bl[nt][1]);
            }
            #pragma unroll
            for (int mt = 0; mt < 2; mt++)
                #pragma unroll
                for (int nt = 0; nt < 4; nt++) {
                    mma8(c[mt][nt], ah[mt], bh[nt]);
                    mma8(c[mt][nt], ah[mt], bl[nt]);
                    mma8(c[mt][nt], al[mt], bh[nt]);
                }
        }
        __syncthreads();
    }
    #pragma unroll
    for (int mt = 0; mt < 2; mt++)
        #pragma unroll
        for (int nt = 0; nt < 4; nt++) {
            int e = wn0 + nt * 8 + 2 * t;
            #pragma unroll
            for (int half = 0; half < 2; half++) {
                int r = M0 + wm0 + mt * 16 + half * 8 + g;
                int bb = r >> 11, s = r & 2047;
                float2 val = make_float2(c[mt][nt][half * 2], c[mt][nt][half * 2 + 1]);
                if (z == 2) {
                    *reinterpret_cast<float2*>(&g_vs[((size_t)bb * Sn + s) * DHn + e]) = val;
                } else {
                    float* dst = (z == 0) ? g_qs : g_ks;
                    int h = blockIdx.x;
                    *reinterpret_cast<float2*>(&dst[(((size_t)(bb * Hn + h)) * Sn + s) * DHn + e]) = val;
                }
            }
        }
}

// ================= Kernel 2: fused attention =================
// QK^T via bf16x3 (hi/lo split staged in smem), PV via single tf32.
// Mask comes from bit-packed g_mbits.
__global__ __launch_bounds__(256) void attn_kernel(float* __restrict__ attn_out)
{
    extern __shared__ char smraw[];
    __nv_bfloat16 (*Qh)[72] = reinterpret_cast<__nv_bfloat16(*)[72]>(smraw);            // 128x72 bf16
    __nv_bfloat16 (*Ql)[72] = reinterpret_cast<__nv_bfloat16(*)[72]>(smraw + 18432);
    __nv_bfloat16 (*Kh)[72] = reinterpret_cast<__nv_bfloat16(*)[72]>(smraw + 36864);    // 64x72
    __nv_bfloat16 (*Kl)[72] = reinterpret_cast<__nv_bfloat16(*)[72]>(smraw + 46080);
    float (*Vs)[72] = reinterpret_cast<float(*)[72]>(smraw + 55296);                    // 64x72 f32
    float (*Ps)[68] = reinterpret_cast<float(*)[68]>(smraw + 73728);                    // 128x68 f32
    unsigned (*m2)[2] = reinterpret_cast<unsigned(*)[2]>(smraw + 108544);               // 128x2
    float* rowsum = reinterpret_cast<float*>(smraw + 109568);                           // 128

    int st = blockIdx.x, h = blockIdx.y, b = blockIdx.z;
    int bh = b * Hn + h;
    int S0 = st * 128;
    int tid = threadIdx.x, warp = tid >> 5, lane = tid & 31;
    int g = lane >> 2, t = lane & 3;
    int wm0 = (warp >> 1) * 32, wn0 = (warp & 1) * 32;

    const float* qsrc = g_qs + ((size_t)bh * Sn + S0) * DHn;
    const float* ksrc = g_ks + (size_t)bh * Sn * DHn;
    const float* vsrc = g_vs + (size_t)b * Sn * DHn;
    const unsigned* msrc = g_mbits + ((size_t)b * Sn + S0) * (Sn / 32);
    float* aout = attn_out + (size_t)bh * Sn * Sn;

    // load Q and split to bf16 hi/lo
    #pragma unroll
    for (int it = 0; it < 8; it++) {
        int i = tid + it * 256;
        int r = i >> 4, c4 = (i & 15) << 2;
        float4 val = *reinterpret_cast<const float4*>(&qsrc[(size_t)r * DHn + c4]);
        __nv_bfloat16 hi, lo;
        bsplit(val.x, hi, lo); Qh[r][c4]   = hi; Ql[r][c4]   = lo;
        bsplit(val.y, hi, lo); Qh[r][c4+1] = hi; Ql[r][c4+1] = lo;
        bsplit(val.z, hi, lo); Qh[r][c4+2] = hi; Ql[r][c4+2] = lo;
        bsplit(val.w, hi, lo); Qh[r][c4+3] = hi; Ql[r][c4+3] = lo;
    }
    if (tid < 128) rowsum[tid] = 0.f;

    float cO[2][4][4];
    #pragma unroll
    for (int mt = 0; mt < 2; mt++)
        #pragma unroll
        for (int nt = 0; nt < 4; nt++)
            #pragma unroll
            for (int i = 0; i < 4; i++) cO[mt][nt][i] = 0.f;
    float rpart[2][2] = {{0.f, 0.f}, {0.f, 0.f}};

    for (int tc = 0; tc < 32; tc++) {
        int T0 = tc * 64;
        // load K (split) + V + mask words
        #pragma unroll
        for (int it = 0; it < 4; it++) {
            int i = tid + it * 256;
            int r = i >> 4, c4 = (i & 15) << 2;
            float4 kv = *reinterpret_cast<const float4*>(&ksrc[(size_t)(T0 + r) * DHn + c4]);
            __nv_bfloat16 hi, lo;
            bsplit(kv.x, hi, lo); Kh[r][c4]   = hi; Kl[r][c4]   = lo;
            bsplit(kv.y, hi, lo); Kh[r][c4+1] = hi; Kl[r][c4+1] = lo;
            bsplit(kv.z, hi, lo); Kh[r][c4+2] = hi; Kl[r][c4+2] = lo;
            bsplit(kv.w, hi, lo); Kh[r][c4+3] = hi; Kl[r][c4+3] = lo;
            float4 vv = *reinterpret_cast<const float4*>(&vsrc[(size_t)(T0 + r) * DHn + c4]);
            Vs[r][c4] = vv.x; Vs[r][c4+1] = vv.y; Vs[r][c4+2] = vv.z; Vs[r][c4+3] = vv.w;
        }
        { // 128 rows x 2 mask words
            int r = tid >> 1, w = tid & 1;
            m2[r][w] = msrc[(size_t)r * (Sn / 32) + (T0 >> 5) + w];
        }
        __syncthreads();

        // ---- QK^T (bf16x3) ----
        float cS[2][4][4];
        #pragma unroll
        for (int mt = 0; mt < 2; mt++)
            #pragma unroll
            for (int nt = 0; nt < 4; nt++)
                #pragma unroll
                for (int i = 0; i < 4; i++) cS[mt][nt][i] = 0.f;
        #pragma unroll
        for (int kk = 0; kk < 4; kk++) {
            int k0 = kk * 16;
            unsigned ah[2][4], al[2][4], bhf[4][2], blf[4][2];
            #pragma unroll
            for (int mt = 0; mt < 2; mt++) {
                int rb = wm0 + mt * 16;
                ah[mt][0] = *reinterpret_cast<const unsigned*>(&Qh[rb + g][k0 + 2*t]);
                ah[mt][1] = *reinterpret_cast<const unsigned*>(&Qh[rb + 8 + g][k0 + 2*t]);
                ah[mt][2] = *reinterpret_cast<const unsigned*>(&Qh[rb + g][k0 + 8 + 2*t]);
                ah[mt][3] = *reinterpret_cast<const unsigned*>(&Qh[rb + 8 + g][k0 + 8 + 2*t]);
                al[mt][0] = *reinterpret_cast<const unsigned*>(&Ql[rb + g][k0 + 2*t]);
                al[mt][1] = *reinterpret_cast<const unsigned*>(&Ql[rb + 8 + g][k0 + 2*t]);
                al[mt][2] = *reinterpret_cast<const unsigned*>(&Ql[rb + g][k0 + 8 + 2*t]);
                al[mt][3] = *reinterpret_cast<const unsigned*>(&Ql[rb + 8 + g][k0 + 8 + 2*t]);
            }
            #pragma unroll
            for (int nt = 0; nt < 4; nt++) {
                int cb = wn0 + nt * 8 + g;
                bhf[nt][0] = *reinterpret_cast<const unsigned*>(&Kh[cb][k0 + 2*t]);
                bhf[nt][1] = *reinterpret_cast<const unsigned*>(&Kh[cb][k0 + 8 + 2*t]);
                blf[nt][0] = *reinterpret_cast<const unsigned*>(&Kl[cb][k0 + 2*t]);
                blf[nt][1] = *reinterpret_cast<const unsigned*>(&Kl[cb][k0 + 8 + 2*t]);
            }
            #pragma unroll
            for (int mt = 0; mt < 2; mt++)
                #pragma unroll
                for (int nt = 0; nt < 4; nt++) {
                    mma16(cS[mt][nt], ah[mt], bhf[nt]);
                    mma16(cS[mt][nt], ah[mt], blf[nt]);
                    mma16(cS[mt][nt], al[mt], bhf[nt]);
                }
        }

        // ---- mask + exp + write attn (unnormalized) + stage P ----
        #pragma unroll
        for (int mt = 0; mt < 2; mt++)
            #pragma unroll
            for (int nt = 0; nt < 4; nt++) {
                int tloc = wn0 + nt * 8 + 2 * t;
                int tg = T0 + tloc;
                #pragma unroll
                for (int half = 0; half < 2; half++) {
                    int rloc = wm0 + mt * 16 + half * 8 + g;
                    int sg = S0 + rloc;
                    unsigned mw = m2[rloc][tloc >> 5];
                    int sh = tloc & 31;
                    float p0 = ((mw >> sh) & 1u)       ? __expf(cS[mt][nt][half * 2]     * 0.125f) : 0.f;
                    float p1 = ((mw >> (sh + 1)) & 1u) ? __expf(cS[mt][nt][half * 2 + 1] * 0.125f) : 0.f;
                    *reinterpret_cast<float2*>(&aout[(size_t)sg * Sn + tg]) = make_float2(p0, p1);
                    *reinterpret_cast<float2*>(&Ps[rloc][tloc]) = make_float2(p0, p1);
                    rpart[mt][half] += p0 + p1;
                }
            }
        __syncthreads();

        // ---- heads += P @ V (tf32) ----
        #pragma unroll
        for (int kk = 0; kk < 8; kk++) {
            int k0 = kk * 8;
            unsigned a[2][4], bf[4][2];
            #pragma unroll
            for (int mt = 0; mt < 2; mt++) {
                int rb = wm0 + mt * 16;
                a[mt][0] = f2tf(Ps[rb + g][k0 + t]);
                a[mt][1] = f2tf(Ps[rb + 8 + g][k0 + t]);
                a[mt][2] = f2tf(Ps[rb + g][k0 + t + 4]);
                a[mt][3] = f2tf(Ps[rb + 8 + g][k0 + t + 4]);
            }
            #pragma unroll
            for (int nt = 0; nt < 4; nt++) {
                int cb = wn0 + nt * 8 + g;
                bf[nt][0] = f2tf(Vs[k0 + t][cb]);
                bf[nt][1] = f2tf(Vs[k0 + t + 4][cb]);
            }
            #pragma unroll
            for (int mt = 0; mt < 2; mt++)
                #pragma unroll
                for (int nt = 0; nt < 4; nt++)
                    mma8(cO[mt][nt], a[mt], bf[nt]);
        }
        __syncthreads();
    }

    // ---- rowsum reduce ----
    #pragma unroll
    for (int mt = 0; mt < 2; mt++)
        #pragma unroll
        for (int half = 0; half < 2; half++) {
            float v = rpart[mt][half];
            v += __shfl_xor_sync(0xffffffffu, v, 1);
            v += __shfl_xor_sync(0xffffffffu, v, 2);
            if (t == 0) atomicAdd(&rowsum[wm0 + mt * 16 + half * 8 + g], v);
        }
    __syncthreads();

    // ---- write heads (scaled by 0.25/rowsum) + rowsum ----
    float* hdst = g_heads + (size_t)bh * Sn * DHn;
    #pragma unroll
    for (int mt = 0; mt < 2; mt++)
        #pragma unroll
        for (int nt = 0; nt < 4; nt++) {
            int e = wn0 + nt * 8 + 2 * t;
            #pragma unroll
            for (int half = 0; half < 2; half++) {
                int rloc = wm0 + mt * 16 + half * 8 + g;
                float inv = 0.25f / rowsum[rloc];
                float2 val = make_float2(cO[mt][nt][half * 2] * inv, cO[mt][nt][half * 2 + 1] * inv);
                *reinterpret_cast<float2*>(&hdst[(size_t)(S0 + rloc) * DHn + e]) = val;
            }
        }
    if (tid < 128) g_rowsum[(size_t)bh * Sn + S0 + tid] = rowsum[tid];
}

// ================= Kernel 3: normalize attn rows =================
__global__ void rescale_kernel(float* __restrict__ attn) {
    int row = blockIdx.x;
    float inv = 1.f / g_rowsum[row];
    float4* p = reinterpret_cast<float4*>(attn + (size_t)row * Sn);
    int tid = threadIdx.x;
    #pragma unroll
    for (int i = 0; i < 2; i++) {
        float4 v = p[tid + i * 256];
        v.x *= inv; v.y *= inv; v.z *= inv; v.w *= inv;
        p[tid + i * 256] = v;
    }
}

// ================= Kernel 4: out = mean_h(heads) @ Wo =================
__global__ __launch_bounds__(256) void final_kernel(
    const float* __restrict__ Wo, float* __restrict__ out)
{
    __shared__ float avg[16][64];
    int r0 = blockIdx.x * 16;
    int tid = threadIdx.x;
    #pragma unroll
    for (int it = 0; it < 4; it++) {
        int i = tid + it * 256;
        int rr = i >> 6, e = i & 63;
        int R = r0 + rr;
        int bb = R >> 11, s = R & 2047;
        size_t base = ((size_t)(bb * Hn) * Sn + s) * DHn + e;
        avg[rr][e] = g_heads[base] + g_heads[base + (size_t)Sn * DHn]
                   + g_heads[base + 2 * (size_t)Sn * DHn] + g_heads[base + 3 * (size_t)Sn * DHn];
    }
    __syncthreads();
    float acc[16];
    #pragma unroll
    for (int i = 0; i < 16; i++) acc[i] = 0.f;
    int d = tid;
    #pragma unroll 16
    for (int e = 0; e < 64; e++) {
        float w = Wo[e * Dn + d];
        #pragma unroll
        for (int i = 0; i < 16; i++) acc[i] += avg[i][e] * w;
    }
    #pragma unroll
    for (int i = 0; i < 16; i++) out[(size_t)(r0 + i) * Dn + d] = acc[i];
}

// ================= launch =================
extern "C" void kernel_launch(void* const* d_in, const int* in_sizes, int n_in,
                              void* d_out, int out_size) {
    const float* q    = (const float*)d_in[0];
    const float* k    = (const float*)d_in[1];
    const float* v    = (const float*)d_in[2];
    const int*   mask = (const int*)  d_in[3];
    const float* Wq   = (const float*)d_in[4];
    const float* Wk   = (const float*)d_in[5];
    const float* Wv   = (const float*)d_in[6];
    const float* Wo   = (const float*)d_in[7];
    float* outp  = (float*)d_out;
    float* attnp = outp + (size_t)Bn * Sn * Dn;   // outputs first, attn second

    (void)in_sizes; (void)n_in; (void)out_size;

    cudaFuncSetAttribute(attn_kernel, cudaFuncAttributeMaxDynamicSharedMemorySize, 110080);

    pack_mask_kernel<<<(Bn * Sn * Sn) / 256, 256>>>(mask);
    proj_kernel<<<dim3(4, 128, 3), 256>>>(q, k, v, Wq, Wk, Wv);
    attn_kernel<<<dim3(16, 4, 8), 256, 110080>>>(attnp);
    rescale_kernel<<<Bn * Hn * Sn, 256>>>(attnp);
    final_kernel<<<(Bn * Sn) / 16, 256>>>(Wo, outp);
}

// round 4
// speedup vs baseline: 1.3656x; 1.1343x over previous
#include <cuda_runtime.h>
#include <cuda_bf16.h>

#define Bn 8
#define Sn 2048
#define Dn 256
#define Hn 4
#define DHn 64

// ---------------- scratch (static device arrays; no allocation) ----------------
__device__ float g_qs[Bn*Hn*Sn*DHn];     // 16 MB  [B,H,S,DH]
__device__ float g_ks[Bn*Hn*Sn*DHn];     // 16 MB  [B,H,S,DH]
__device__ float g_vs[Bn*Sn*DHn];        //  4 MB  [B,S,DH]
__device__ float g_heads[Bn*Hn*Sn*DHn];  // 16 MB  [B,H,S,DH]  (already scaled by 1/(4*rowsum))
__device__ float g_rowsum[Bn*Hn*Sn];     // 256 KB
__device__ unsigned g_mbits[Bn*Sn*(Sn/32)]; // 16.8 MB bit-packed mask

// ---------------- helpers ----------------
__device__ __forceinline__ unsigned f2tf(float x) {
    unsigned u;
    asm("cvt.rna.tf32.f32 %0, %1;" : "=r"(u) : "f"(x));
    return u;
}
__device__ __forceinline__ void mma8(float* c, const unsigned* a, const unsigned* b) {
    asm volatile("mma.sync.aligned.m16n8k8.row.col.f32.tf32.tf32.f32 "
        "{%0,%1,%2,%3}, {%4,%5,%6,%7}, {%8,%9}, {%0,%1,%2,%3};\n"
        : "+f"(c[0]), "+f"(c[1]), "+f"(c[2]), "+f"(c[3])
        : "r"(a[0]), "r"(a[1]), "r"(a[2]), "r"(a[3]), "r"(b[0]), "r"(b[1]));
}
__device__ __forceinline__ void mma16(float* c, const unsigned* a, const unsigned* b) {
    asm volatile("mma.sync.aligned.m16n8k16.row.col.f32.bf16.bf16.f32 "
        "{%0,%1,%2,%3}, {%4,%5,%6,%7}, {%8,%9}, {%0,%1,%2,%3};\n"
        : "+f"(c[0]), "+f"(c[1]), "+f"(c[2]), "+f"(c[3])
        : "r"(a[0]), "r"(a[1]), "r"(a[2]), "r"(a[3]), "r"(b[0]), "r"(b[1]));
}
__device__ __forceinline__ void bsplit(float x, __nv_bfloat16 &hi, __nv_bfloat16 &lo) {
    hi = __float2bfloat16_rn(x);
    lo = __float2bfloat16_rn(x - __bfloat162float(hi));
}

// FMA-pipe exp(s/8): avoids MUFU (rt_SMSP=8, the binding pipe of R3's attn kernel).
// exp(s/8) = 2^(s*log2e/8).  Magic-constant round to int, degree-5 Taylor for the
// fraction, exponent splice via integer add.  rel err ~2e-6.
__device__ __forceinline__ float fexp8(float s) {
    const float c = 0.18033688011112042f;   // log2(e)/8
    const float MAGIC = 12582912.0f;        // 1.5 * 2^23
    float t = fmaf(s, c, MAGIC);
    float k = t - MAGIC;
    float f = fmaf(s, c, -k);               // f in [-0.5, 0.5]
    float p = 1.3333558146e-3f;
    p = fmaf(p, f, 9.6181291076e-3f);
    p = fmaf(p, f, 5.5504108665e-2f);
    p = fmaf(p, f, 2.4022650696e-1f);
    p = fmaf(p, f, 6.9314718056e-1f);
    p = fmaf(p, f, 1.0f);
    int ik = __float_as_int(t) << 23;       // k << 23 (two's complement safe)
    return __int_as_float(__float_as_int(p) + ik);
}

// ================= Kernel 0: bit-pack the mask =================
__global__ void pack_mask_kernel(const int* __restrict__ mask) {
    size_t i = (size_t)blockIdx.x * 256 + threadIdx.x;
    int m = mask[i] != 0;
    unsigned bal = __ballot_sync(0xffffffffu, m);
    if ((threadIdx.x & 31) == 0) g_mbits[i >> 5] = bal;
}

// ================= Kernel 1: projections (qs, ks, vs) via bf16x3 GEMM =================
// z=0: qs = q @ Wq[h]   z=1: ks = k @ Wk[h]   z=2: vs = v @ Wv
// Tile: 128 (M) x 64 (N) x 32 (Kchunk). 8 warps as 4x2, warp tile 32x32.
__global__ __launch_bounds__(256) void proj_kernel(
    const float* __restrict__ q, const float* __restrict__ k, const float* __restrict__ v,
    const float* __restrict__ Wq, const float* __restrict__ Wk, const float* __restrict__ Wv)
{
    int z = blockIdx.z;
    if (z == 2 && blockIdx.x > 0) return;
    __shared__ __nv_bfloat16 Ah[128][40];
    __shared__ __nv_bfloat16 Al[128][40];
    __shared__ __nv_bfloat16 Bh[64][40];   // stored as [n][k]
    __shared__ __nv_bfloat16 Bl[64][40];

    const float* X = (z == 0) ? q : (z == 1) ? k : v;
    const float* W = (z == 0) ? (Wq + (size_t)blockIdx.x * Dn * DHn)
                   : (z == 1) ? (Wk + (size_t)blockIdx.x * Dn * DHn) : Wv;
    int M0 = blockIdx.y * 128;
    int tid = threadIdx.x;
    int warp = tid >> 5, lane = tid & 31;
    int g = lane >> 2, t = lane & 3;
    int wm0 = (warp >> 1) * 32, wn0 = (warp & 1) * 32;

    float c[2][4][4];
    #pragma unroll
    for (int mt = 0; mt < 2; mt++)
        #pragma unroll
        for (int nt = 0; nt < 4; nt++)
            #pragma unroll
            for (int i = 0; i < 4; i++) c[mt][nt][i] = 0.f;

    for (int kc = 0; kc < 8; kc++) {
        int K0 = kc * 32;
        #pragma unroll
        for (int it = 0; it < 4; it++) {
            int i = tid + it * 256;
            int r = i >> 3, c4 = (i & 7) << 2;
            float4 val = *reinterpret_cast<const float4*>(&X[(size_t)(M0 + r) * Dn + K0 + c4]);
            __nv_bfloat16 hi, lo;
            bsplit(val.x, hi, lo); Ah[r][c4]   = hi; Al[r][c4]   = lo;
            bsplit(val.y, hi, lo); Ah[r][c4+1] = hi; Al[r][c4+1] = lo;
            bsplit(val.z, hi, lo); Ah[r][c4+2] = hi; Al[r][c4+2] = lo;
            bsplit(val.w, hi, lo); Ah[r][c4+3] = hi; Al[r][c4+3] = lo;
        }
        #pragma unroll
        for (int it = 0; it < 2; it++) {
            int i = tid + it * 256;
            int r = i >> 4, c4 = (i & 15) << 2;   // r = k row (0..31), c4 = n
            float4 val = *reinterpret_cast<const float4*>(&W[(size_t)(K0 + r) * DHn + c4]);
            __nv_bfloat16 hi, lo;
            bsplit(val.x, hi, lo); Bh[c4][r]   = hi; Bl[c4][r]   = lo;
            bsplit(val.y, hi, lo); Bh[c4+1][r] = hi; Bl[c4+1][r] = lo;
            bsplit(val.z, hi, lo); Bh[c4+2][r] = hi; Bl[c4+2][r] = lo;
            bsplit(val.w, hi, lo); Bh[c4+3][r] = hi; Bl[c4+3][r] = lo;
        }
        __syncthreads();
        #pragma unroll
        for (int kk = 0; kk < 2; kk++) {
            int k0 = kk * 16;
            unsigned ah[2][4], al[2][4], bh[4][2], bl[4][2];
            #pragma unroll
            for (int mt = 0; mt < 2; mt++) {
                int rb = wm0 + mt * 16;
                ah[mt][0] = *reinterpret_cast<const unsigned*>(&Ah[rb + g][k0 + 2*t]);
                ah[mt][1] = *reinterpret_cast<const unsigned*>(&Ah[rb + 8 + g][k0 + 2*t]);
                ah[mt][2] = *reinterpret_cast<const unsigned*>(&Ah[rb + g][k0 + 8 + 2*t]);
                ah[mt][3] = *reinterpret_cast<const unsigned*>(&Ah[rb + 8 + g][k0 + 8 + 2*t]);
                al[mt][0] = *reinterpret_cast<const unsigned*>(&Al[rb + g][k0 + 2*t]);
                al[mt][1] = *reinterpret_cast<const unsigned*>(&Al[rb + 8 + g][k0 + 2*t]);
                al[mt][2] = *reinterpret_cast<const unsigned*>(&Al[rb + g][k0 + 8 + 2*t]);
                al[mt][3] = *reinterpret_cast<const unsigned*>(&Al[rb + 8 + g][k0 + 8 + 2*t]);
            }
            #pragma unroll
            for (int nt = 0; nt < 4; nt++) {
                int cb = wn0 + nt * 8 + g;
                bh[nt][0] = *reinterpret_cast<const unsigned*>(&Bh[cb][k0 + 2*t]);
                bh[nt][1] = *reinterpret_cast<const unsigned*>(&Bh[cb][k0 + 8 + 2*t]);
                bl[nt][0] = *reinterpret_cast<const unsigned*>(&Bl[cb][k0 + 2*t]);
                bl[nt][1] = *reinterpret_cast<const unsigned*>(&Bl[cb][k0 + 8 + 2*t]);
            }
            #pragma unroll
            for (int mt = 0; mt < 2; mt++)
                #pragma unroll
                for (int nt = 0; nt < 4; nt++) {
                    mma16(c[mt][nt], ah[mt], bh[nt]);
                    mma16(c[mt][nt], ah[mt], bl[nt]);
                    mma16(c[mt][nt], al[mt], bh[nt]);
                }
        }
        __syncthreads();
    }
    #pragma unroll
    for (int mt = 0; mt < 2; mt++)
        #pragma unroll
        for (int nt = 0; nt < 4; nt++) {
            int e = wn0 + nt * 8 + 2 * t;
            #pragma unroll
            for (int half = 0; half < 2; half++) {
                int r = M0 + wm0 + mt * 16 + half * 8 + g;
                int bb = r >> 11, s = r & 2047;
                float2 val = make_float2(c[mt][nt][half * 2], c[mt][nt][half * 2 + 1]);
                if (z == 2) {
                    *reinterpret_cast<float2*>(&g_vs[((size_t)bb * Sn + s) * DHn + e]) = val;
                } else {
                    float* dst = (z == 0) ? g_qs : g_ks;
                    int h = blockIdx.x;
                    *reinterpret_cast<float2*>(&dst[(((size_t)(bb * Hn + h)) * Sn + s) * DHn + e]) = val;
                }
            }
        }
}

// ================= Kernel 2: fused attention =================
// QK^T via bf16x3 (hi/lo split staged in smem), PV via single tf32.
// exp on the FMA pipe (fexp8), mask from bit-packed g_mbits.
__global__ __launch_bounds__(256) void attn_kernel(float* __restrict__ attn_out)
{
    extern __shared__ char smraw[];
    __nv_bfloat16 (*Qh)[72] = reinterpret_cast<__nv_bfloat16(*)[72]>(smraw);            // 128x72 bf16
    __nv_bfloat16 (*Ql)[72] = reinterpret_cast<__nv_bfloat16(*)[72]>(smraw + 18432);
    __nv_bfloat16 (*Kh)[72] = reinterpret_cast<__nv_bfloat16(*)[72]>(smraw + 36864);    // 64x72
    __nv_bfloat16 (*Kl)[72] = reinterpret_cast<__nv_bfloat16(*)[72]>(smraw + 46080);
    float (*Vs)[72] = reinterpret_cast<float(*)[72]>(smraw + 55296);                    // 64x72 f32
    float (*Ps)[68] = reinterpret_cast<float(*)[68]>(smraw + 73728);                    // 128x68 f32
    unsigned (*m2)[2] = reinterpret_cast<unsigned(*)[2]>(smraw + 108544);               // 128x2
    float* rowsum = reinterpret_cast<float*>(smraw + 109568);                           // 128

    int st = blockIdx.x, h = blockIdx.y, b = blockIdx.z;
    int bh = b * Hn + h;
    int S0 = st * 128;
    int tid = threadIdx.x, warp = tid >> 5, lane = tid & 31;
    int g = lane >> 2, t = lane & 3;
    int wm0 = (warp >> 1) * 32, wn0 = (warp & 1) * 32;

    const float* qsrc = g_qs + ((size_t)bh * Sn + S0) * DHn;
    const float* ksrc = g_ks + (size_t)bh * Sn * DHn;
    const float* vsrc = g_vs + (size_t)b * Sn * DHn;
    const unsigned* msrc = g_mbits + ((size_t)b * Sn + S0) * (Sn / 32);
    float* aout = attn_out + (size_t)bh * Sn * Sn;

    // load Q and split to bf16 hi/lo
    #pragma unroll
    for (int it = 0; it < 8; it++) {
        int i = tid + it * 256;
        int r = i >> 4, c4 = (i & 15) << 2;
        float4 val = *reinterpret_cast<const float4*>(&qsrc[(size_t)r * DHn + c4]);
        __nv_bfloat16 hi, lo;
        bsplit(val.x, hi, lo); Qh[r][c4]   = hi; Ql[r][c4]   = lo;
        bsplit(val.y, hi, lo); Qh[r][c4+1] = hi; Ql[r][c4+1] = lo;
        bsplit(val.z, hi, lo); Qh[r][c4+2] = hi; Ql[r][c4+2] = lo;
        bsplit(val.w, hi, lo); Qh[r][c4+3] = hi; Ql[r][c4+3] = lo;
    }
    if (tid < 128) rowsum[tid] = 0.f;

    float cO[2][4][4];
    #pragma unroll
    for (int mt = 0; mt < 2; mt++)
        #pragma unroll
        for (int nt = 0; nt < 4; nt++)
            #pragma unroll
            for (int i = 0; i < 4; i++) cO[mt][nt][i] = 0.f;
    float rpart[2][2] = {{0.f, 0.f}, {0.f, 0.f}};

    for (int tc = 0; tc < 32; tc++) {
        int T0 = tc * 64;
        // load K (split) + V + mask words
        #pragma unroll
        for (int it = 0; it < 4; it++) {
            int i = tid + it * 256;
            int r = i >> 4, c4 = (i & 15) << 2;
            float4 kv = *reinterpret_cast<const float4*>(&ksrc[(size_t)(T0 + r) * DHn + c4]);
            __nv_bfloat16 hi, lo;
            bsplit(kv.x, hi, lo); Kh[r][c4]   = hi; Kl[r][c4]   = lo;
            bsplit(kv.y, hi, lo); Kh[r][c4+1] = hi; Kl[r][c4+1] = lo;
            bsplit(kv.z, hi, lo); Kh[r][c4+2] = hi; Kl[r][c4+2] = lo;
            bsplit(kv.w, hi, lo); Kh[r][c4+3] = hi; Kl[r][c4+3] = lo;
            float4 vv = *reinterpret_cast<const float4*>(&vsrc[(size_t)(T0 + r) * DHn + c4]);
            Vs[r][c4] = vv.x; Vs[r][c4+1] = vv.y; Vs[r][c4+2] = vv.z; Vs[r][c4+3] = vv.w;
        }
        { // 128 rows x 2 mask words
            int r = tid >> 1, w = tid & 1;
            m2[r][w] = msrc[(size_t)r * (Sn / 32) + (T0 >> 5) + w];
        }
        __syncthreads();

        // ---- QK^T (bf16x3) ----
        float cS[2][4][4];
        #pragma unroll
        for (int mt = 0; mt < 2; mt++)
            #pragma unroll
            for (int nt = 0; nt < 4; nt++)
                #pragma unroll
                for (int i = 0; i < 4; i++) cS[mt][nt][i] = 0.f;
        #pragma unroll
        for (int kk = 0; kk < 4; kk++) {
            int k0 = kk * 16;
            unsigned ah[2][4], al[2][4], bhf[4][2], blf[4][2];
            #pragma unroll
            for (int mt = 0; mt < 2; mt++) {
                int rb = wm0 + mt * 16;
                ah[mt][0] = *reinterpret_cast<const unsigned*>(&Qh[rb + g][k0 + 2*t]);
                ah[mt][1] = *reinterpret_cast<const unsigned*>(&Qh[rb + 8 + g][k0 + 2*t]);
                ah[mt][2] = *reinterpret_cast<const unsigned*>(&Qh[rb + g][k0 + 8 + 2*t]);
                ah[mt][3] = *reinterpret_cast<const unsigned*>(&Qh[rb + 8 + g][k0 + 8 + 2*t]);
                al[mt][0] = *reinterpret_cast<const unsigned*>(&Ql[rb + g][k0 + 2*t]);
                al[mt][1] = *reinterpret_cast<const unsigned*>(&Ql[rb + 8 + g][k0 + 2*t]);
                al[mt][2] = *reinterpret_cast<const unsigned*>(&Ql[rb + g][k0 + 8 + 2*t]);
                al[mt][3] = *reinterpret_cast<const unsigned*>(&Ql[rb + 8 + g][k0 + 8 + 2*t]);
            }
            #pragma unroll
            for (int nt = 0; nt < 4; nt++) {
                int cb = wn0 + nt * 8 + g;
                bhf[nt][0] = *reinterpret_cast<const unsigned*>(&Kh[cb][k0 + 2*t]);
                bhf[nt][1] = *reinterpret_cast<const unsigned*>(&Kh[cb][k0 + 8 + 2*t]);
                blf[nt][0] = *reinterpret_cast<const unsigned*>(&Kl[cb][k0 + 2*t]);
                blf[nt][1] = *reinterpret_cast<const unsigned*>(&Kl[cb][k0 + 8 + 2*t]);
            }
            #pragma unroll
            for (int mt = 0; mt < 2; mt++)
                #pragma unroll
                for (int nt = 0; nt < 4; nt++) {
                    mma16(cS[mt][nt], ah[mt], bhf[nt]);
                    mma16(cS[mt][nt], ah[mt], blf[nt]);
                    mma16(cS[mt][nt], al[mt], bhf[nt]);
                }
        }

        // ---- mask + exp (FMA pipe) + write attn (unnormalized) + stage P ----
        #pragma unroll
        for (int mt = 0; mt < 2; mt++)
            #pragma unroll
            for (int nt = 0; nt < 4; nt++) {
                int tloc = wn0 + nt * 8 + 2 * t;
                int tg = T0 + tloc;
                #pragma unroll
                for (int half = 0; half < 2; half++) {
                    int rloc = wm0 + mt * 16 + half * 8 + g;
                    int sg = S0 + rloc;
                    unsigned mw = m2[rloc][tloc >> 5];
                    int sh = tloc & 31;
                    float e0 = fexp8(cS[mt][nt][half * 2]);
                    float e1 = fexp8(cS[mt][nt][half * 2 + 1]);
                    float p0 = ((mw >> sh) & 1u)       ? e0 : 0.f;
                    float p1 = ((mw >> (sh + 1)) & 1u) ? e1 : 0.f;
                    *reinterpret_cast<float2*>(&aout[(size_t)sg * Sn + tg]) = make_float2(p0, p1);
                    *reinterpret_cast<float2*>(&Ps[rloc][tloc]) = make_float2(p0, p1);
                    rpart[mt][half] += p0 + p1;
                }
            }
        __syncthreads();

        // ---- heads += P @ V (tf32) ----
        #pragma unroll
        for (int kk = 0; kk < 8; kk++) {
            int k0 = kk * 8;
            unsigned a[2][4], bf[4][2];
            #pragma unroll
            for (int mt = 0; mt < 2; mt++) {
                int rb = wm0 + mt * 16;
                a[mt][0] = f2tf(Ps[rb + g][k0 + t]);
                a[mt][1] = f2tf(Ps[rb + 8 + g][k0 + t]);
                a[mt][2] = f2tf(Ps[rb + g][k0 + t + 4]);
                a[mt][3] = f2tf(Ps[rb + 8 + g][k0 + t + 4]);
            }
            #pragma unroll
            for (int nt = 0; nt < 4; nt++) {
                int cb = wn0 + nt * 8 + g;
                bf[nt][0] = f2tf(Vs[k0 + t][cb]);
                bf[nt][1] = f2tf(Vs[k0 + t + 4][cb]);
            }
            #pragma unroll
            for (int mt = 0; mt < 2; mt++)
                #pragma unroll
                for (int nt = 0; nt < 4; nt++)
                    mma8(cO[mt][nt], a[mt], bf[nt]);
        }
        __syncthreads();
    }

    // ---- rowsum reduce ----
    #pragma unroll
    for (int mt = 0; mt < 2; mt++)
        #pragma unroll
        for (int half = 0; half < 2; half++) {
            float v = rpart[mt][half];
            v += __shfl_xor_sync(0xffffffffu, v, 1);
            v += __shfl_xor_sync(0xffffffffu, v, 2);
            if (t == 0) atomicAdd(&rowsum[wm0 + mt * 16 + half * 8 + g], v);
        }
    __syncthreads();

    // ---- write heads (scaled by 0.25/rowsum) + rowsum ----
    float* hdst = g_heads + (size_t)bh * Sn * DHn;
    #pragma unroll
    for (int mt = 0; mt < 2; mt++)
        #pragma unroll
        for (int nt = 0; nt < 4; nt++) {
            int e = wn0 + nt * 8 + 2 * t;
            #pragma unroll
            for (int half = 0; half < 2; half++) {
                int rloc = wm0 + mt * 16 + half * 8 + g;
                float inv = 0.25f / rowsum[rloc];
                float2 val = make_float2(cO[mt][nt][half * 2] * inv, cO[mt][nt][half * 2 + 1] * inv);
                *reinterpret_cast<float2*>(&hdst[(size_t)(S0 + rloc) * DHn + e]) = val;
            }
        }
    if (tid < 128) g_rowsum[(size_t)bh * Sn + S0 + tid] = rowsum[tid];
}

// ================= Kernel 3: normalize attn rows =================
__global__ void rescale_kernel(float* __restrict__ attn) {
    int row = blockIdx.x;
    float inv = 1.f / g_rowsum[row];
    float4* p = reinterpret_cast<float4*>(attn + (size_t)row * Sn);
    int tid = threadIdx.x;
    #pragma unroll
    for (int i = 0; i < 2; i++) {
        float4 v = p[tid + i * 256];
        v.x *= inv; v.y *= inv; v.z *= inv; v.w *= inv;
        p[tid + i * 256] = v;
    }
}

// ================= Kernel 4: out = mean_h(heads) @ Wo =================
__global__ __launch_bounds__(256) void final_kernel(
    const float* __restrict__ Wo, float* __restrict__ out)
{
    __shared__ float avg[16][64];
    int r0 = blockIdx.x * 16;
    int tid = threadIdx.x;
    #pragma unroll
    for (int it = 0; it < 4; it++) {
        int i = tid + it * 256;
        int rr = i >> 6, e = i & 63;
        int R = r0 + rr;
        int bb = R >> 11, s = R & 2047;
        size_t base = ((size_t)(bb * Hn) * Sn + s) * DHn + e;
        avg[rr][e] = g_heads[base] + g_heads[base + (size_t)Sn * DHn]
                   + g_heads[base + 2 * (size_t)Sn * DHn] + g_heads[base + 3 * (size_t)Sn * DHn];
    }
    __syncthreads();
    float acc[16];
    #pragma unroll
    for (int i = 0; i < 16; i++) acc[i] = 0.f;
    int d = tid;
    #pragma unroll 16
    for (int e = 0; e < 64; e++) {
        float w = Wo[e * Dn + d];
        #pragma unroll
        for (int i = 0; i < 16; i++) acc[i] += avg[i][e] * w;
    }
    #pragma unroll
    for (int i = 0; i < 16; i++) out[(size_t)(r0 + i) * Dn + d] = acc[i];
}

// ================= launch =================
extern "C" void kernel_launch(void* const* d_in, const int* in_sizes, int n_in,
                              void* d_out, int out_size) {
    const float* q    = (const float*)d_in[0];
    const float* k    = (const float*)d_in[1];
    const float* v    = (const float*)d_in[2];
    const int*   mask = (const int*)  d_in[3];
    const float* Wq   = (const float*)d_in[4];
    const float* Wk   = (const float*)d_in[5];
    const float* Wv   = (const float*)d_in[6];
    const float* Wo   = (const float*)d_in[7];
    float* outp  = (float*)d_out;
    float* attnp = outp + (size_t)Bn * Sn * Dn;   // outputs first, attn second

    (void)in_sizes; (void)n_in; (void)out_size;

    cudaFuncSetAttribute(attn_kernel, cudaFuncAttributeMaxDynamicSharedMemorySize, 110080);

    pack_mask_kernel<<<(Bn * Sn * Sn) / 256, 256>>>(mask);
    proj_kernel<<<dim3(4, 128, 3), 256>>>(q, k, v, Wq, Wk, Wv);
    attn_kernel<<<dim3(16, 4, 8), 256, 110080>>>(attnp);
    rescale_kernel<<<Bn * Hn * Sn, 256>>>(attnp);
    final_kernel<<<(Bn * Sn) / 16, 256>>>(Wo, outp);
}